// round 16
// baseline (speedup 1.0000x reference)
#include <cuda_runtime.h>
#include <cuda_fp16.h>
#include <cstdint>

#define TT 8192
#define DD 2048
#define NCH 128
#define CL (TT/NCH)   // 64

#define BM 128
#define BN 128
#define BKH 64                    // K halves per stage = 128B row
#define NKT (DD / BKH)            // 32
#define STAGE_B 32768             // A 16KB + B 16KB
#define SMEM_DYN (2 * STAGE_B)    // 65536

// ---------------- scratch ----------------
__device__ __half  g_h0[(size_t)TT*DD];
__device__ __half  g_h1[(size_t)TT*DD];
__device__ __half  g_h2[(size_t)TT*DD];
__device__ __half  g_t0h[(size_t)TT*DD];
__device__ __half  g_rh[(size_t)TT*DD];
__device__ __half  g_kh[(size_t)TT*DD];
__device__ __half  g_vh[(size_t)TT*DD];
__device__ __half  g_rzh[(size_t)TT*DD];
__device__ __half  g_wh[(size_t)7*DD*DD];
__device__ float g_sa[NCH*DD], g_sb[NCH*DD], g_sp[NCH*DD];
__device__ float g_pa[NCH*DD], g_pb[NCH*DD], g_pp[NCH*DD];

// ---------------- helpers ----------------
__device__ __forceinline__ uint32_t saddr(const void* p) {
    return (uint32_t)__cvta_generic_to_shared(p);
}
__device__ __forceinline__ void cp_async16(uint32_t s, const void* g) {
    asm volatile("cp.async.cg.shared.global [%0], [%1], 16;" :: "r"(s), "l"(g));
}
__device__ __forceinline__ void cp_commit() {
    asm volatile("cp.async.commit_group;");
}
template <int N> __device__ __forceinline__ void cp_wait() {
    asm volatile("cp.async.wait_group %0;" :: "n"(N));
}
__device__ __forceinline__ void ldsm_x4(uint32_t r[4], uint32_t addr) {
    asm volatile("ldmatrix.sync.aligned.m8n8.x4.shared.b16 {%0,%1,%2,%3}, [%4];"
        : "=r"(r[0]), "=r"(r[1]), "=r"(r[2]), "=r"(r[3]) : "r"(addr));
}
__device__ __forceinline__ void mma16(float d[4], const uint32_t a[4],
                                      uint32_t b0, uint32_t b1) {
    asm volatile(
        "mma.sync.aligned.m16n8k16.row.col.f32.f16.f16.f32 "
        "{%0,%1,%2,%3}, {%4,%5,%6,%7}, {%8,%9}, {%0,%1,%2,%3};"
        : "+f"(d[0]), "+f"(d[1]), "+f"(d[2]), "+f"(d[3])
        : "r"(a[0]), "r"(a[1]), "r"(a[2]), "r"(a[3]), "r"(b0), "r"(b1));
}
__device__ __forceinline__ void gdc_wait() {
    asm volatile("griddepcontrol.wait;" ::: "memory");
}
__device__ __forceinline__ void gdc_launch() {
    asm volatile("griddepcontrol.launch_dependents;");
}
#define SWZ(x) ((x) ^ (((x) >> 3) & 0x70))

// ---------------- elementwise kernels ----------------
struct WConvJob { const float4* src[4]; __half2* dst; };
__global__ __launch_bounds__(256) void wconvN_kernel(WConvJob job) {
    const int per = DD * DD / 4;
    int i = blockIdx.x * 256 + threadIdx.x;
    int w = i / per;
    int j = i - w * per;
    float4 v = job.src[w][j];
    __half2* o = job.dst + (size_t)w * (DD * DD / 2) + (size_t)j * 2;
    o[0] = __floats2half2_rn(v.x, v.y);
    o[1] = __floats2half2_rn(v.z, v.w);
}

template <typename XT>
__device__ __forceinline__ float4 load4(const XT* row, int c);
template <> __device__ __forceinline__ float4 load4<float>(const float* row, int c) {
    return reinterpret_cast<const float4*>(row)[c];
}
template <> __device__ __forceinline__ float4 load4<__half>(const __half* row, int c) {
    const __half2* h = reinterpret_cast<const __half2*>(row);
    float2 a = __half22float2(h[c * 2]);
    float2 b = __half22float2(h[c * 2 + 1]);
    return make_float4(a.x, a.y, b.x, b.y);
}

// fused LayerNorm + N-way token-shift lerp, 4 output rows per block.
template <int N, typename XT>
__global__ __launch_bounds__(256) void ln_mix4_kernel(
    const XT* __restrict__ x,
    const float* __restrict__ gw, const float* __restrict__ gb,
    const float* __restrict__ m0, const float* __restrict__ m1,
    const float* __restrict__ m2,
    __half2* __restrict__ o0, __half2* __restrict__ o1, __half2* __restrict__ o2) {
    gdc_wait();
    const int t0 = blockIdx.x * 4;
    const int tid = threadIdx.x;
    const int wid = tid >> 5, lane = tid & 31;

    float4 va[5][2];
    __shared__ float ws[5][2][8];

#pragma unroll
    for (int r = 0; r < 5; r++) {
        const int g = (t0 + r + TT - 1) & (TT - 1);
        const XT* row = x + (size_t)g * DD;
        float s = 0.f, s2 = 0.f;
#pragma unroll
        for (int i = 0; i < 2; i++) {
            float4 a = load4<XT>(row, tid + i * 256);
            va[r][i] = a;
            s  += a.x + a.y + a.z + a.w;
            s2 += a.x*a.x + a.y*a.y + a.z*a.z + a.w*a.w;
        }
#pragma unroll
        for (int o = 16; o; o >>= 1) {
            s  += __shfl_xor_sync(0xffffffffu, s,  o);
            s2 += __shfl_xor_sync(0xffffffffu, s2, o);
        }
        if (!lane) { ws[r][0][wid] = s; ws[r][1][wid] = s2; }
    }
    __syncthreads();

    float mean[5], inv[5];
#pragma unroll
    for (int r = 0; r < 5; r++) {
        float S = 0.f, S2 = 0.f;
#pragma unroll
        for (int i = 0; i < 8; i++) { S += ws[r][0][i]; S2 += ws[r][1][i]; }
        mean[r] = S * (1.0f / DD);
        inv[r]  = rsqrtf(S2 * (1.0f / DD) - mean[r] * mean[r] + 1e-5f);
    }
    gdc_launch();

    const float4* g4 = reinterpret_cast<const float4*>(gw);
    const float4* b4 = reinterpret_cast<const float4*>(gb);
#pragma unroll
    for (int i = 0; i < 2; i++) {
        const int c = tid + i * 256;
        const float4 g = g4[c], b = b4[c];
#pragma unroll
        for (int r = 0; r < 5; r++) {
            float4 v = va[r][i];
            v.x = (v.x - mean[r]) * inv[r] * g.x + b.x;
            v.y = (v.y - mean[r]) * inv[r] * g.y + b.y;
            v.z = (v.z - mean[r]) * inv[r] * g.z + b.z;
            v.w = (v.w - mean[r]) * inv[r] * g.w + b.w;
            va[r][i] = v;
        }
    }

#pragma unroll
    for (int j = 0; j < 4; j++) {
        const size_t base2 = (size_t)(t0 + j) * (DD / 2);
#pragma unroll
        for (int i = 0; i < 2; i++) {
            const int c = tid + i * 256;
            const float4 p = va[j][i], a = va[j + 1][i];
            const float4 mm0 = reinterpret_cast<const float4*>(m0)[c];
            o0[base2 + c * 2]     = __floats2half2_rn(p.x + mm0.x * (a.x - p.x), p.y + mm0.y * (a.y - p.y));
            o0[base2 + c * 2 + 1] = __floats2half2_rn(p.z + mm0.z * (a.z - p.z), p.w + mm0.w * (a.w - p.w));
            const float4 mm1 = reinterpret_cast<const float4*>(m1)[c];
            o1[base2 + c * 2]     = __floats2half2_rn(p.x + mm1.x * (a.x - p.x), p.y + mm1.y * (a.y - p.y));
            o1[base2 + c * 2 + 1] = __floats2half2_rn(p.z + mm1.z * (a.z - p.z), p.w + mm1.w * (a.w - p.w));
            if (N == 3) {
                const float4 mm2 = reinterpret_cast<const float4*>(m2)[c];
                o2[base2 + c * 2]     = __floats2half2_rn(p.x + mm2.x * (a.x - p.x), p.y + mm2.y * (a.y - p.y));
                o2[base2 + c * 2 + 1] = __floats2half2_rn(p.z + mm2.z * (a.z - p.z), p.w + mm2.w * (a.w - p.w));
            }
        }
    }
}

// ---------------- WKV chunked scan (fp16 k/v, half2 = 2 channels/thread) ----------------
__global__ __launch_bounds__(256) void wkv_phase1(const __half2* __restrict__ k,
                                                  const __half2* __restrict__ v,
                                                  const float2* __restrict__ td) {
    gdc_wait();
    const int c = blockIdx.x * 256 + threadIdx.x;
    const int ch = blockIdx.y;
    const float2 tdv = td[c];
    const float wx = -__expf(tdv.x), wy = -__expf(tdv.y);
    float ax = 0.f, ay = 0.f, bx = 0.f, by = 0.f, px = -1e38f, py = -1e38f;
    size_t base = (size_t)ch * CL * (DD / 2) + c;
#pragma unroll 4
    for (int i = 0; i < CL; i++) {
        const float2 kt = __half22float2(k[base + (size_t)i * (DD / 2)]);
        const float2 vt = __half22float2(v[base + (size_t)i * (DD / 2)]);
        float ww = px + wx;
        float p2 = fmaxf(ww, kt.x);
        float e1 = __expf(ww - p2), e2 = __expf(kt.x - p2);
        ax = e1 * ax + e2 * vt.x; bx = e1 * bx + e2; px = p2;
        ww = py + wy;
        p2 = fmaxf(ww, kt.y);
        e1 = __expf(ww - p2); e2 = __expf(kt.y - p2);
        ay = e1 * ay + e2 * vt.y; by = e1 * by + e2; py = p2;
    }
    const int idx = ch * DD + 2 * c;
    g_sa[idx] = ax; g_sa[idx + 1] = ay;
    g_sb[idx] = bx; g_sb[idx + 1] = by;
    g_sp[idx] = px; g_sp[idx + 1] = py;
}

__global__ __launch_bounds__(256) void wkv_phase2(const float* __restrict__ td) {
    gdc_wait();
    int c = blockIdx.x * 256 + threadIdx.x;
    float w = -__expf(td[c]);
    float clw = (float)CL * w;
    float aa = 0.f, bb = 0.f, pp = -1e38f;
#pragma unroll 1
    for (int ch0 = 0; ch0 < NCH; ch0 += 4) {
        float la[4], lb[4], lp[4];
#pragma unroll
        for (int j = 0; j < 4; j++) {
            const int idx = (ch0 + j) * DD + c;
            la[j] = g_sa[idx]; lb[j] = g_sb[idx]; lp[j] = g_sp[idx];
        }
#pragma unroll
        for (int j = 0; j < 4; j++) {
            const int idx = (ch0 + j) * DD + c;
            g_pa[idx] = aa; g_pb[idx] = bb; g_pp[idx] = pp;
            float pd = pp + clw;
            float p = fmaxf(pd, lp[j]);
            float e1 = __expf(pd - p), e2 = __expf(lp[j] - p);
            aa = e1 * aa + e2 * la[j];
            bb = e1 * bb + e2 * lb[j];
            pp = p;
        }
    }
}

__global__ __launch_bounds__(256) void wkv_phase3(const __half2* __restrict__ k,
                                                  const __half2* __restrict__ v,
                                                  const __half2* __restrict__ r,
                                                  const float2* __restrict__ tf,
                                                  const float2* __restrict__ td,
                                                  __half2* __restrict__ out) {
    const int c = blockIdx.x * 256 + threadIdx.x;
    const int ch = blockIdx.y;
    const float2 tdv = td[c];
    const float wx = -__expf(tdv.x), wy = -__expf(tdv.y);
    const float2 uv = tf[c];
    const int idx = ch * DD + 2 * c;
    float ax = g_pa[idx], ay = g_pa[idx + 1];
    float bx = g_pb[idx], by = g_pb[idx + 1];
    float px = g_pp[idx], py = g_pp[idx + 1];
    size_t base = (size_t)ch * CL * (DD / 2) + c;
#pragma unroll 4
    for (int i = 0; i < CL; i++) {
        const size_t off = base + (size_t)i * (DD / 2);
        const float2 kt = __half22float2(k[off]);
        const float2 vt = __half22float2(v[off]);
        const float2 rr = __half22float2(r[off]);
        float ww = uv.x + kt.x;
        float p = fmaxf(px, ww);
        float e1 = __expf(px - p), e2 = __expf(ww - p);
        float ox = (e1 * ax + e2 * vt.x) / (e1 * bx + e2);
        ww = px + wx;
        p = fmaxf(ww, kt.x);
        e1 = __expf(ww - p); e2 = __expf(kt.x - p);
        ax = e1 * ax + e2 * vt.x; bx = e1 * bx + e2; px = p;
        ww = uv.y + kt.y;
        p = fmaxf(py, ww);
        e1 = __expf(py - p); e2 = __expf(ww - p);
        float oy = (e1 * ay + e2 * vt.y) / (e1 * by + e2);
        ww = py + wy;
        p = fmaxf(ww, kt.y);
        e1 = __expf(ww - p); e2 = __expf(kt.y - p);
        ay = e1 * ay + e2 * vt.y; by = e1 * by + e2; py = p;
        out[off] = __floats2half2_rn(ox * rr.x, oy * rr.y);
    }
}

// ---------------- fp16 mma.sync GEMM, z-batched jobs, PDL-aware ----------------
struct GJob {
    const __half* A; const __half* W; const float* bias;
    const float* auxf; const __half* auxh; const __half* aux2h;
    void* out; int mode;
};
struct GJobs { GJob j[3]; };

__global__ __launch_bounds__(128, 3) void gemm_h(GJobs jobs) {
    const GJob J = jobs.j[blockIdx.z];
    extern __shared__ __align__(1024) char smem[];
    const uint32_t sb = saddr(smem);
    const int tid = threadIdx.x;
    const int warp = tid >> 5, lane = tid & 31;
    const int bm = blockIdx.x * BM;
    const int bn = blockIdx.y * BN;
    const int wm = (warp >> 1) * 64;
    const int wn = (warp & 1) * 64;

    const uint32_t d0 = SWZ((uint32_t)((tid >> 3) * 128 + (tid & 7) * 16));
    const __half* gA = J.A + (size_t)bm * DD + (size_t)(tid >> 3) * DD + (tid & 7) * 8;
    const __half* gB = J.W + (size_t)bn * DD + (size_t)(tid >> 3) * DD + (tid & 7) * 8;

    float acc[4][8][4];
#pragma unroll
    for (int i = 0; i < 4; i++)
#pragma unroll
        for (int j = 0; j < 8; j++)
#pragma unroll
            for (int q = 0; q < 4; q++) acc[i][j][q] = 0.f;

    // PDL prologue: prefetch weights (independent of upstream), then gate
#pragma unroll
    for (int i = 0; i < 8; i++)
        cp_async16(sb + 16384 + i * 2048 + d0, gB + (size_t)(i * 16) * DD);
    cp_commit();
    gdc_wait();
#pragma unroll
    for (int i = 0; i < 8; i++)
        cp_async16(sb + i * 2048 + d0, gA + (size_t)(i * 16) * DD);
    cp_commit();

    // strength-reduced producer pointers: advance by BKH each kt
    gA += BKH;
    gB += BKH;

    auto load_stage_adv = [&](uint32_t stbase) {
#pragma unroll
        for (int i = 0; i < 8; i++) {
            const size_t so = (size_t)(i * 16) * DD;
            cp_async16(stbase + i * 2048,         gA + so);
            cp_async16(stbase + 16384 + i * 2048, gB + so);
        }
        gA += BKH;
        gB += BKH;
    };

    const int lrow = lane & 15;
    const uint32_t kxor = (uint32_t)((lane & 7) << 4);
    const uint32_t khi  = (uint32_t)((lane >> 4) * 16);
    uint32_t arow_off[4], brow_off[4];
#pragma unroll
    for (int mi = 0; mi < 4; mi++) arow_off[mi] = sb + (uint32_t)((wm + mi * 16 + lrow) * 128);
#pragma unroll
    for (int g = 0; g < 4; g++) brow_off[g] = sb + (uint32_t)(16384 + (wn + g * 16 + lrow) * 128);
    // hoisted per-(stage,ks) address combos: combo[s][ks] = s*STAGE_B + ((ks*32+khi)^kxor)
    uint32_t combo[2][4];
#pragma unroll
    for (int s = 0; s < 2; s++)
#pragma unroll
        for (int ks = 0; ks < 4; ks++)
            combo[s][ks] = (uint32_t)(s * STAGE_B) + (((uint32_t)(ks * 32) + khi) ^ kxor);

    for (int kt = 0; kt < NKT; kt++) {
        cp_wait<0>();
        __syncthreads();
        if (kt + 1 < NKT) load_stage_adv(sb + ((kt + 1) & 1) * STAGE_B + d0);
        cp_commit();

        const uint32_t* cb = combo[kt & 1];
#pragma unroll
        for (int ks = 0; ks < 4; ks++) {
            const uint32_t kpart = cb[ks];
            uint32_t af[4][4], bf[4][4];
#pragma unroll
            for (int mi = 0; mi < 4; mi++) ldsm_x4(af[mi], arow_off[mi] + kpart);
#pragma unroll
            for (int g = 0; g < 4; g++)   ldsm_x4(bf[g],  brow_off[g] + kpart);
#pragma unroll
            for (int mi = 0; mi < 4; mi++)
#pragma unroll
                for (int g = 0; g < 4; g++) {
                    mma16(acc[mi][2 * g],     af[mi], bf[g][0], bf[g][2]);
                    mma16(acc[mi][2 * g + 1], af[mi], bf[g][1], bf[g][3]);
                }
        }
    }

    gdc_launch();

    const int mode = J.mode;
    const float* bias = J.bias;
#pragma unroll
    for (int mi = 0; mi < 4; mi++) {
        const uint32_t r0 = (uint32_t)(bm + wm + mi * 16 + (lane >> 2));
#pragma unroll
        for (int ni = 0; ni < 8; ni++) {
            const uint32_t c0 = (uint32_t)(bn + wn + ni * 8 + (lane & 3) * 2);
            const float b0 = bias[c0], b1 = bias[c0 + 1];
            const uint32_t i0 = r0 * (uint32_t)DD + c0;
            const uint32_t i1 = (r0 + 8) * (uint32_t)DD + c0;
            float v[4];
            v[0] = acc[mi][ni][0] + b0;
            v[1] = acc[mi][ni][1] + b1;
            v[2] = acc[mi][ni][2] + b0;
            v[3] = acc[mi][ni][3] + b1;
            if (mode == 1) {
#pragma unroll
                for (int q = 0; q < 4; q++) v[q] = 1.0f / (1.0f + __expf(-v[q]));
            } else if (mode == 2) {
#pragma unroll
                for (int q = 0; q < 4; q++) { float t = v[q] > 0.f ? v[q] : 0.f; v[q] = t * t; }
            } else if (mode == 3) {
                v[0] += J.auxf[i0]; v[1] += J.auxf[i0 + 1];
                v[2] += J.auxf[i1]; v[3] += J.auxf[i1 + 1];
            } else if (mode == 4) {
                const float2 r01 = __half22float2(*reinterpret_cast<const __half2*>(J.auxh + i0));
                const float2 r23 = __half22float2(*reinterpret_cast<const __half2*>(J.auxh + i1));
                const float2 z01 = __half22float2(*reinterpret_cast<const __half2*>(J.aux2h + i0));
                const float2 z23 = __half22float2(*reinterpret_cast<const __half2*>(J.aux2h + i1));
                v[0] = v[0] * r01.x + z01.x;
                v[1] = v[1] * r01.y + z01.y;
                v[2] = v[2] * r23.x + z23.x;
                v[3] = v[3] * r23.y + z23.y;
            }
            if (mode <= 3) {
                __half* oh = (__half*)J.out;
                *reinterpret_cast<__half2*>(oh + i0) = __floats2half2_rn(v[0], v[1]);
                *reinterpret_cast<__half2*>(oh + i1) = __floats2half2_rn(v[2], v[3]);
            } else {
                float* o = (float*)J.out;
                o[i0] = v[0]; o[i0 + 1] = v[1];
                o[i1] = v[2]; o[i1 + 1] = v[3];
            }
        }
    }
}

// ---------------- host orchestration ----------------
extern "C" void kernel_launch(void* const* d_in, const int* in_sizes, int n_in,
                              void* d_out, int out_size) {
    const float* x = (const float*)d_in[0];
    const float* w_src[7];
    const float* b_src[7];
    for (int i = 0; i < 7; i++) {
        w_src[i] = (const float*)d_in[1 + 2 * i];
        b_src[i] = (const float*)d_in[2 + 2 * i];
    }
    const float* ln1g = (const float*)d_in[15];
    const float* ln1b = (const float*)d_in[16];
    const float* ln2g = (const float*)d_in[17];
    const float* ln2b = (const float*)d_in[18];
    const float* mixk = (const float*)d_in[19];
    const float* mixv = (const float*)d_in[20];
    const float* mixr = (const float*)d_in[21];
    const float* fmk  = (const float*)d_in[22];
    const float* fmr  = (const float*)d_in[23];
    const float* tf   = (const float*)d_in[24];
    const float* td   = (const float*)d_in[25];
    float* out = (float*)d_out;

    __half *p_h0, *p_h1, *p_h2, *p_t0h, *p_rh, *p_kh, *p_vh, *p_rzh, *p_wh;
    cudaGetSymbolAddress((void**)&p_h0,  g_h0);
    cudaGetSymbolAddress((void**)&p_h1,  g_h1);
    cudaGetSymbolAddress((void**)&p_h2,  g_h2);
    cudaGetSymbolAddress((void**)&p_t0h, g_t0h);
    cudaGetSymbolAddress((void**)&p_rh,  g_rh);
    cudaGetSymbolAddress((void**)&p_kh,  g_kh);
    cudaGetSymbolAddress((void**)&p_vh,  g_vh);
    cudaGetSymbolAddress((void**)&p_rzh, g_rzh);
    cudaGetSymbolAddress((void**)&p_wh,  g_wh);

    cudaFuncSetAttribute(gemm_h, cudaFuncAttributeMaxDynamicSharedMemorySize, SMEM_DYN);

    cudaStream_t s2;
    cudaStreamCreateWithFlags(&s2, cudaStreamNonBlocking);
    cudaEvent_t ev0, evW, evM, evR;
    cudaEventCreateWithFlags(&ev0, cudaEventDisableTiming);
    cudaEventCreateWithFlags(&evW, cudaEventDisableTiming);
    cudaEventCreateWithFlags(&evM, cudaEventDisableTiming);
    cudaEventCreateWithFlags(&evR, cudaEventDisableTiming);

    dim3 gwkv(DD / 512, NCH);
    const __half* W[7];
    for (int i = 0; i < 7; i++) W[i] = p_wh + (size_t)i * DD * DD;

    cudaLaunchAttribute pdl_attr[1];
    pdl_attr[0].id = cudaLaunchAttributeProgrammaticStreamSerialization;
    pdl_attr[0].val.programmaticStreamSerializationAllowed = 1;
    auto launch_gemm_pdl = [&](dim3 grid, const GJobs& js, cudaStream_t st) {
        cudaLaunchConfig_t cfg{};
        cfg.gridDim = grid; cfg.blockDim = dim3(128, 1, 1);
        cfg.dynamicSmemBytes = SMEM_DYN; cfg.stream = st;
        cfg.attrs = pdl_attr; cfg.numAttrs = 1;
        cudaLaunchKernelEx(&cfg, gemm_h, js);
    };

    // fork: weight conversion on s2 (attn weights first -> early evW), ln_mix1 on main
    cudaEventRecord(ev0, 0);
    cudaStreamWaitEvent(s2, ev0, 0);
    {
        WConvJob wj{};
        wj.src[0] = (const float4*)w_src[0];
        wj.src[1] = (const float4*)w_src[1];
        wj.src[2] = (const float4*)w_src[2];
        wj.src[3] = (const float4*)w_src[2];
        wj.dst = (__half2*)p_wh;
        wconvN_kernel<<<3 * (DD * DD / 4) / 256, 256, 0, s2>>>(wj);
    }
    cudaEventRecord(evW, s2);
    {
        WConvJob wj{};
        wj.src[0] = (const float4*)w_src[3];
        wj.src[1] = (const float4*)w_src[4];
        wj.src[2] = (const float4*)w_src[5];
        wj.src[3] = (const float4*)w_src[6];
        wj.dst = (__half2*)(p_wh + (size_t)3 * DD * DD);
        wconvN_kernel<<<4 * (DD * DD / 4) / 256, 256, 0, s2>>>(wj);
    }

    ln_mix4_kernel<3, float><<<TT / 4, 256>>>(x, ln1g, ln1b, mixk, mixv, mixr,
                                              (__half2*)p_h0, (__half2*)p_h1, (__half2*)p_h2);
    cudaEventRecord(evM, 0);

    cudaStreamWaitEvent(s2, evM, 0);
    {
        GJobs js{};
        js.j[0] = { p_h2, W[2], b_src[2], nullptr, nullptr, nullptr, (void*)p_rh, 1 };
        gemm_h<<<dim3(TT / BM, DD / BN, 1), 128, SMEM_DYN, s2>>>(js);
    }
    cudaEventRecord(evR, s2);

    cudaStreamWaitEvent(0, evW, 0);
    {
        GJobs js{};
        js.j[0] = { p_h0, W[0], b_src[0], nullptr, nullptr, nullptr, (void*)p_kh, 0 };
        js.j[1] = { p_h1, W[1], b_src[1], nullptr, nullptr, nullptr, (void*)p_vh, 0 };
        gemm_h<<<dim3(TT / BM, DD / BN, 2), 128, SMEM_DYN>>>(js);
    }
    {
        cudaLaunchConfig_t cfg{};
        cfg.gridDim = gwkv; cfg.blockDim = dim3(256, 1, 1);
        cfg.dynamicSmemBytes = 0; cfg.stream = 0;
        cfg.attrs = pdl_attr; cfg.numAttrs = 1;
        cudaLaunchKernelEx(&cfg, wkv_phase1,
                           (const __half2*)p_kh, (const __half2*)p_vh, (const float2*)td);
    }
    {
        cudaLaunchConfig_t cfg{};
        cfg.gridDim = dim3(DD / 256, 1, 1); cfg.blockDim = dim3(256, 1, 1);
        cfg.dynamicSmemBytes = 0; cfg.stream = 0;
        cfg.attrs = pdl_attr; cfg.numAttrs = 1;
        cudaLaunchKernelEx(&cfg, wkv_phase2, td);
    }

    cudaStreamWaitEvent(0, evR, 0);
    wkv_phase3<<<gwkv, 256>>>((const __half2*)p_kh, (const __half2*)p_vh,
                              (const __half2*)p_rh, (const float2*)tf, (const float2*)td,
                              (__half2*)p_t0h);

    {
        GJobs js{};
        js.j[0] = { p_t0h, W[3], b_src[3], x, nullptr, nullptr, (void*)p_rzh, 3 };
        launch_gemm_pdl(dim3(TT / BM, DD / BN, 1), js, 0);
    }

    {
        cudaLaunchConfig_t cfg{};
        cfg.gridDim = dim3(TT / 4, 1, 1); cfg.blockDim = dim3(256, 1, 1);
        cfg.dynamicSmemBytes = 0; cfg.stream = 0;
        cfg.attrs = pdl_attr; cfg.numAttrs = 1;
        cudaLaunchKernelEx(&cfg, ln_mix4_kernel<2, __half>,
                           (const __half*)p_rzh, ln2g, ln2b, fmr, fmk, (const float*)nullptr,
                           (__half2*)p_h0, (__half2*)p_h1, (__half2*)nullptr);
    }

    {
        GJobs js{};
        js.j[0] = { p_h0, W[6], b_src[6], nullptr, nullptr, nullptr, (void*)p_rh,  1 };
        js.j[1] = { p_h1, W[4], b_src[4], nullptr, nullptr, nullptr, (void*)p_t0h, 2 };
        launch_gemm_pdl(dim3(TT / BM, DD / BN, 2), js, 0);
    }

    {
        GJobs js{};
        js.j[0] = { p_t0h, W[5], b_src[5], nullptr, p_rh, p_rzh, (void*)out, 4 };
        launch_gemm_pdl(dim3(TT / BM, DD / BN, 1), js, 0);
    }
}

// round 17
// speedup vs baseline: 1.3635x; 1.3635x over previous
#include <cuda_runtime.h>
#include <cuda_fp16.h>
#include <cstdint>

#define TT 8192
#define DD 2048
#define NCH 128
#define CL (TT/NCH)   // 64

#define BM 128
#define BN 128
#define BKH 64                    // K halves per stage = 128B row
#define NKT (DD / BKH)            // 32
#define STAGE_B 32768             // A 16KB + B 16KB
#define SMEM_DYN (2 * STAGE_B)    // 65536

// ---------------- scratch ----------------
__device__ __half  g_h0[(size_t)TT*DD];
__device__ __half  g_h1[(size_t)TT*DD];
__device__ __half  g_h2[(size_t)TT*DD];
__device__ __half  g_t0h[(size_t)TT*DD];
__device__ __half  g_rh[(size_t)TT*DD];
__device__ __half  g_kh[(size_t)TT*DD];
__device__ __half  g_vh[(size_t)TT*DD];
__device__ __half  g_rzh[(size_t)TT*DD];
__device__ __half  g_wh[(size_t)7*DD*DD];
__device__ float g_sa[NCH*DD], g_sb[NCH*DD], g_sp[NCH*DD];
__device__ float g_pa[NCH*DD], g_pb[NCH*DD], g_pp[NCH*DD];

// ---------------- helpers ----------------
__device__ __forceinline__ uint32_t saddr(const void* p) {
    return (uint32_t)__cvta_generic_to_shared(p);
}
__device__ __forceinline__ void cp_async16(uint32_t s, const void* g) {
    asm volatile("cp.async.cg.shared.global [%0], [%1], 16;" :: "r"(s), "l"(g));
}
__device__ __forceinline__ void cp_commit() {
    asm volatile("cp.async.commit_group;");
}
template <int N> __device__ __forceinline__ void cp_wait() {
    asm volatile("cp.async.wait_group %0;" :: "n"(N));
}
__device__ __forceinline__ void ldsm_x4(uint32_t r[4], uint32_t addr) {
    asm volatile("ldmatrix.sync.aligned.m8n8.x4.shared.b16 {%0,%1,%2,%3}, [%4];"
        : "=r"(r[0]), "=r"(r[1]), "=r"(r[2]), "=r"(r[3]) : "r"(addr));
}
__device__ __forceinline__ void mma16(float d[4], const uint32_t a[4],
                                      uint32_t b0, uint32_t b1) {
    asm volatile(
        "mma.sync.aligned.m16n8k16.row.col.f32.f16.f16.f32 "
        "{%0,%1,%2,%3}, {%4,%5,%6,%7}, {%8,%9}, {%0,%1,%2,%3};"
        : "+f"(d[0]), "+f"(d[1]), "+f"(d[2]), "+f"(d[3])
        : "r"(a[0]), "r"(a[1]), "r"(a[2]), "r"(a[3]), "r"(b0), "r"(b1));
}
__device__ __forceinline__ void gdc_wait() {
    asm volatile("griddepcontrol.wait;" ::: "memory");
}
__device__ __forceinline__ void gdc_launch() {
    asm volatile("griddepcontrol.launch_dependents;");
}
#define SWZ(x) ((x) ^ (((x) >> 3) & 0x70))

// ---------------- elementwise kernels ----------------
// convert up to 4 weight matrices fp32 -> fp16
struct WConvJob { const float4* src[4]; __half2* dst; };
__global__ __launch_bounds__(256) void wconvN_kernel(WConvJob job) {
    const int per = DD * DD / 4;
    int i = blockIdx.x * 256 + threadIdx.x;
    int w = i / per;
    int j = i - w * per;
    float4 v = job.src[w][j];
    __half2* o = job.dst + (size_t)w * (DD * DD / 2) + (size_t)j * 2;
    o[0] = __floats2half2_rn(v.x, v.y);
    o[1] = __floats2half2_rn(v.z, v.w);
}

// typed row loader: 4 consecutive floats at element index 4*c
template <typename XT>
__device__ __forceinline__ float4 load4(const XT* row, int c);
template <> __device__ __forceinline__ float4 load4<float>(const float* row, int c) {
    return reinterpret_cast<const float4*>(row)[c];
}
template <> __device__ __forceinline__ float4 load4<__half>(const __half* row, int c) {
    const __half2* h = reinterpret_cast<const __half2*>(row);
    float2 a = __half22float2(h[c * 2]);
    float2 b = __half22float2(h[c * 2 + 1]);
    return make_float4(a.x, a.y, b.x, b.y);
}

// fused LayerNorm + N-way token-shift lerp, 4 output rows per block.
template <int N, typename XT>
__global__ __launch_bounds__(256) void ln_mix4_kernel(
    const XT* __restrict__ x,
    const float* __restrict__ gw, const float* __restrict__ gb,
    const float* __restrict__ m0, const float* __restrict__ m1,
    const float* __restrict__ m2,
    __half2* __restrict__ o0, __half2* __restrict__ o1, __half2* __restrict__ o2) {
    gdc_wait();
    const int t0 = blockIdx.x * 4;
    const int tid = threadIdx.x;
    const int wid = tid >> 5, lane = tid & 31;

    float4 va[5][2];
    __shared__ float ws[5][2][8];

#pragma unroll
    for (int r = 0; r < 5; r++) {
        const int g = (t0 + r + TT - 1) & (TT - 1);
        const XT* row = x + (size_t)g * DD;
        float s = 0.f, s2 = 0.f;
#pragma unroll
        for (int i = 0; i < 2; i++) {
            float4 a = load4<XT>(row, tid + i * 256);
            va[r][i] = a;
            s  += a.x + a.y + a.z + a.w;
            s2 += a.x*a.x + a.y*a.y + a.z*a.z + a.w*a.w;
        }
#pragma unroll
        for (int o = 16; o; o >>= 1) {
            s  += __shfl_xor_sync(0xffffffffu, s,  o);
            s2 += __shfl_xor_sync(0xffffffffu, s2, o);
        }
        if (!lane) { ws[r][0][wid] = s; ws[r][1][wid] = s2; }
    }
    __syncthreads();

    float mean[5], inv[5];
#pragma unroll
    for (int r = 0; r < 5; r++) {
        float S = 0.f, S2 = 0.f;
#pragma unroll
        for (int i = 0; i < 8; i++) { S += ws[r][0][i]; S2 += ws[r][1][i]; }
        mean[r] = S * (1.0f / DD);
        inv[r]  = rsqrtf(S2 * (1.0f / DD) - mean[r] * mean[r] + 1e-5f);
    }
    gdc_launch();

    const float4* g4 = reinterpret_cast<const float4*>(gw);
    const float4* b4 = reinterpret_cast<const float4*>(gb);
#pragma unroll
    for (int i = 0; i < 2; i++) {
        const int c = tid + i * 256;
        const float4 g = g4[c], b = b4[c];
#pragma unroll
        for (int r = 0; r < 5; r++) {
            float4 v = va[r][i];
            v.x = (v.x - mean[r]) * inv[r] * g.x + b.x;
            v.y = (v.y - mean[r]) * inv[r] * g.y + b.y;
            v.z = (v.z - mean[r]) * inv[r] * g.z + b.z;
            v.w = (v.w - mean[r]) * inv[r] * g.w + b.w;
            va[r][i] = v;
        }
    }

#pragma unroll
    for (int j = 0; j < 4; j++) {
        const size_t base2 = (size_t)(t0 + j) * (DD / 2);
#pragma unroll
        for (int i = 0; i < 2; i++) {
            const int c = tid + i * 256;
            const float4 p = va[j][i], a = va[j + 1][i];
            const float4 mm0 = reinterpret_cast<const float4*>(m0)[c];
            o0[base2 + c * 2]     = __floats2half2_rn(p.x + mm0.x * (a.x - p.x), p.y + mm0.y * (a.y - p.y));
            o0[base2 + c * 2 + 1] = __floats2half2_rn(p.z + mm0.z * (a.z - p.z), p.w + mm0.w * (a.w - p.w));
            const float4 mm1 = reinterpret_cast<const float4*>(m1)[c];
            o1[base2 + c * 2]     = __floats2half2_rn(p.x + mm1.x * (a.x - p.x), p.y + mm1.y * (a.y - p.y));
            o1[base2 + c * 2 + 1] = __floats2half2_rn(p.z + mm1.z * (a.z - p.z), p.w + mm1.w * (a.w - p.w));
            if (N == 3) {
                const float4 mm2 = reinterpret_cast<const float4*>(m2)[c];
                o2[base2 + c * 2]     = __floats2half2_rn(p.x + mm2.x * (a.x - p.x), p.y + mm2.y * (a.y - p.y));
                o2[base2 + c * 2 + 1] = __floats2half2_rn(p.z + mm2.z * (a.z - p.z), p.w + mm2.w * (a.w - p.w));
            }
        }
    }
}

// ---------------- WKV chunked scan (fp16 k/v, half2 = 2 channels/thread) ----------------
__global__ __launch_bounds__(256) void wkv_phase1(const __half2* __restrict__ k,
                                                  const __half2* __restrict__ v,
                                                  const float2* __restrict__ td) {
    gdc_wait();
    const int c = blockIdx.x * 256 + threadIdx.x;
    const int ch = blockIdx.y;
    const float2 tdv = td[c];
    const float wx = -__expf(tdv.x), wy = -__expf(tdv.y);
    float ax = 0.f, ay = 0.f, bx = 0.f, by = 0.f, px = -1e38f, py = -1e38f;
    size_t base = (size_t)ch * CL * (DD / 2) + c;
#pragma unroll 4
    for (int i = 0; i < CL; i++) {
        const float2 kt = __half22float2(k[base + (size_t)i * (DD / 2)]);
        const float2 vt = __half22float2(v[base + (size_t)i * (DD / 2)]);
        float ww = px + wx;
        float p2 = fmaxf(ww, kt.x);
        float e1 = __expf(ww - p2), e2 = __expf(kt.x - p2);
        ax = e1 * ax + e2 * vt.x; bx = e1 * bx + e2; px = p2;
        ww = py + wy;
        p2 = fmaxf(ww, kt.y);
        e1 = __expf(ww - p2); e2 = __expf(kt.y - p2);
        ay = e1 * ay + e2 * vt.y; by = e1 * by + e2; py = p2;
    }
    const int idx = ch * DD + 2 * c;
    g_sa[idx] = ax; g_sa[idx + 1] = ay;
    g_sb[idx] = bx; g_sb[idx + 1] = by;
    g_sp[idx] = px; g_sp[idx + 1] = py;
}

// cross-chunk exclusive scan with 4-chunk load batching (MLP 12)
__global__ __launch_bounds__(256) void wkv_phase2(const float* __restrict__ td) {
    gdc_wait();
    int c = blockIdx.x * 256 + threadIdx.x;
    float w = -__expf(td[c]);
    float clw = (float)CL * w;
    float aa = 0.f, bb = 0.f, pp = -1e38f;
#pragma unroll 1
    for (int ch0 = 0; ch0 < NCH; ch0 += 4) {
        float la[4], lb[4], lp[4];
#pragma unroll
        for (int j = 0; j < 4; j++) {
            const int idx = (ch0 + j) * DD + c;
            la[j] = g_sa[idx]; lb[j] = g_sb[idx]; lp[j] = g_sp[idx];
        }
#pragma unroll
        for (int j = 0; j < 4; j++) {
            const int idx = (ch0 + j) * DD + c;
            g_pa[idx] = aa; g_pb[idx] = bb; g_pp[idx] = pp;
            float pd = pp + clw;
            float p = fmaxf(pd, lp[j]);
            float e1 = __expf(pd - p), e2 = __expf(lp[j] - p);
            aa = e1 * aa + e2 * la[j];
            bb = e1 * bb + e2 * lb[j];
            pp = p;
        }
    }
}

__global__ __launch_bounds__(256) void wkv_phase3(const __half2* __restrict__ k,
                                                  const __half2* __restrict__ v,
                                                  const __half2* __restrict__ r,
                                                  const float2* __restrict__ tf,
                                                  const float2* __restrict__ td,
                                                  __half2* __restrict__ out) {
    const int c = blockIdx.x * 256 + threadIdx.x;
    const int ch = blockIdx.y;
    const float2 tdv = td[c];
    const float wx = -__expf(tdv.x), wy = -__expf(tdv.y);
    const float2 uv = tf[c];
    const int idx = ch * DD + 2 * c;
    float ax = g_pa[idx], ay = g_pa[idx + 1];
    float bx = g_pb[idx], by = g_pb[idx + 1];
    float px = g_pp[idx], py = g_pp[idx + 1];
    size_t base = (size_t)ch * CL * (DD / 2) + c;
#pragma unroll 4
    for (int i = 0; i < CL; i++) {
        const size_t off = base + (size_t)i * (DD / 2);
        const float2 kt = __half22float2(k[off]);
        const float2 vt = __half22float2(v[off]);
        const float2 rr = __half22float2(r[off]);
        float ww = uv.x + kt.x;
        float p = fmaxf(px, ww);
        float e1 = __expf(px - p), e2 = __expf(ww - p);
        float ox = (e1 * ax + e2 * vt.x) / (e1 * bx + e2);
        ww = px + wx;
        p = fmaxf(ww, kt.x);
        e1 = __expf(ww - p); e2 = __expf(kt.x - p);
        ax = e1 * ax + e2 * vt.x; bx = e1 * bx + e2; px = p;
        ww = uv.y + kt.y;
        p = fmaxf(py, ww);
        e1 = __expf(py - p); e2 = __expf(ww - p);
        float oy = (e1 * ay + e2 * vt.y) / (e1 * by + e2);
        ww = py + wy;
        p = fmaxf(ww, kt.y);
        e1 = __expf(ww - p); e2 = __expf(kt.y - p);
        ay = e1 * ay + e2 * vt.y; by = e1 * by + e2; py = p;
        out[off] = __floats2half2_rn(ox * rr.x, oy * rr.y);
    }
}

// ---------------- fp16 mma.sync GEMM, z-batched jobs, PDL-aware ----------------
// mode 0: plain(->half)  1: sigmoid(->half)  2: relu^2(->half)
// mode 3: +auxf (f32 aux, ->half)  4: *auxh + aux2h (->f32 out)
struct GJob {
    const __half* A; const __half* W; const float* bias;
    const float* auxf; const __half* auxh; const __half* aux2h;
    void* out; int mode;
};
struct GJobs { GJob j[3]; };

__global__ __launch_bounds__(128, 3) void gemm_h(GJobs jobs) {
    const GJob J = jobs.j[blockIdx.z];
    extern __shared__ __align__(1024) char smem[];
    const uint32_t sb = saddr(smem);
    const int tid = threadIdx.x;
    const int warp = tid >> 5, lane = tid & 31;
    const int bm = blockIdx.x * BM;
    const int bn = blockIdx.y * BN;
    const int wm = (warp >> 1) * 64;
    const int wn = (warp & 1) * 64;

    const uint32_t d0 = SWZ((uint32_t)((tid >> 3) * 128 + (tid & 7) * 16));
    const __half* gA = J.A + (size_t)bm * DD + (size_t)(tid >> 3) * DD + (tid & 7) * 8;
    const __half* gB = J.W + (size_t)bn * DD + (size_t)(tid >> 3) * DD + (tid & 7) * 8;

    float acc[4][8][4];
#pragma unroll
    for (int i = 0; i < 4; i++)
#pragma unroll
        for (int j = 0; j < 8; j++)
#pragma unroll
            for (int q = 0; q < 4; q++) acc[i][j][q] = 0.f;

    // PDL prologue: prefetch weights (independent of upstream), then gate
#pragma unroll
    for (int i = 0; i < 8; i++)
        cp_async16(sb + 16384 + i * 2048 + d0, gB + (size_t)(i * 16) * DD);
    cp_commit();
    gdc_wait();
#pragma unroll
    for (int i = 0; i < 8; i++)
        cp_async16(sb + i * 2048 + d0, gA + (size_t)(i * 16) * DD);
    cp_commit();

    auto load_stage = [&](int kt) {
        const uint32_t st = sb + (kt & 1) * STAGE_B + d0;
        const int kk = kt * BKH;
#pragma unroll
        for (int i = 0; i < 8; i++) {
            const size_t so = (size_t)(i * 16) * DD + kk;
            cp_async16(st + i * 2048,         gA + so);
            cp_async16(st + 16384 + i * 2048, gB + so);
        }
    };

    const int lrow = lane & 15;
    const uint32_t kxor = (uint32_t)((lane & 7) << 4);
    const uint32_t khi  = (uint32_t)((lane >> 4) * 16);
    uint32_t arow_off[4], brow_off[4];
#pragma unroll
    for (int mi = 0; mi < 4; mi++) arow_off[mi] = (uint32_t)((wm + mi * 16 + lrow) * 128);
#pragma unroll
    for (int g = 0; g < 4; g++) brow_off[g] = (uint32_t)(16384 + (wn + g * 16 + lrow) * 128);

    for (int kt = 0; kt < NKT; kt++) {
        cp_wait<0>();
        __syncthreads();
        if (kt + 1 < NKT) load_stage(kt + 1);
        cp_commit();

        const uint32_t st = sb + (kt & 1) * STAGE_B;
#pragma unroll
        for (int ks = 0; ks < 4; ks++) {
            const uint32_t kpart = ((uint32_t)(ks * 32) + khi) ^ kxor;
            uint32_t af[4][4], bf[4][4];
#pragma unroll
            for (int mi = 0; mi < 4; mi++) ldsm_x4(af[mi], st + arow_off[mi] + kpart);
#pragma unroll
            for (int g = 0; g < 4; g++)   ldsm_x4(bf[g],  st + brow_off[g] + kpart);
#pragma unroll
            for (int mi = 0; mi < 4; mi++)
#pragma unroll
                for (int g = 0; g < 4; g++) {
                    mma16(acc[mi][2 * g],     af[mi], bf[g][0], bf[g][2]);
                    mma16(acc[mi][2 * g + 1], af[mi], bf[g][1], bf[g][3]);
                }
        }
    }

    gdc_launch();

    const int mode = J.mode;
    const float* bias = J.bias;
#pragma unroll
    for (int mi = 0; mi < 4; mi++) {
        const uint32_t r0 = (uint32_t)(bm + wm + mi * 16 + (lane >> 2));
#pragma unroll
        for (int ni = 0; ni < 8; ni++) {
            const uint32_t c0 = (uint32_t)(bn + wn + ni * 8 + (lane & 3) * 2);
            const float b0 = bias[c0], b1 = bias[c0 + 1];
            const uint32_t i0 = r0 * (uint32_t)DD + c0;
            const uint32_t i1 = (r0 + 8) * (uint32_t)DD + c0;
            float v[4];
            v[0] = acc[mi][ni][0] + b0;
            v[1] = acc[mi][ni][1] + b1;
            v[2] = acc[mi][ni][2] + b0;
            v[3] = acc[mi][ni][3] + b1;
            if (mode == 1) {
#pragma unroll
                for (int q = 0; q < 4; q++) v[q] = 1.0f / (1.0f + __expf(-v[q]));
            } else if (mode == 2) {
#pragma unroll
                for (int q = 0; q < 4; q++) { float t = v[q] > 0.f ? v[q] : 0.f; v[q] = t * t; }
            } else if (mode == 3) {
                v[0] += J.auxf[i0]; v[1] += J.auxf[i0 + 1];
                v[2] += J.auxf[i1]; v[3] += J.auxf[i1 + 1];
            } else if (mode == 4) {
                const float2 r01 = __half22float2(*reinterpret_cast<const __half2*>(J.auxh + i0));
                const float2 r23 = __half22float2(*reinterpret_cast<const __half2*>(J.auxh + i1));
                const float2 z01 = __half22float2(*reinterpret_cast<const __half2*>(J.aux2h + i0));
                const float2 z23 = __half22float2(*reinterpret_cast<const __half2*>(J.aux2h + i1));
                v[0] = v[0] * r01.x + z01.x;
                v[1] = v[1] * r01.y + z01.y;
                v[2] = v[2] * r23.x + z23.x;
                v[3] = v[3] * r23.y + z23.y;
            }
            if (mode <= 3) {
                __half* oh = (__half*)J.out;
                *reinterpret_cast<__half2*>(oh + i0) = __floats2half2_rn(v[0], v[1]);
                *reinterpret_cast<__half2*>(oh + i1) = __floats2half2_rn(v[2], v[3]);
            } else {
                float* o = (float*)J.out;
                o[i0] = v[0]; o[i0 + 1] = v[1];
                o[i1] = v[2]; o[i1 + 1] = v[3];
            }
        }
    }
}

// ---------------- host orchestration ----------------
extern "C" void kernel_launch(void* const* d_in, const int* in_sizes, int n_in,
                              void* d_out, int out_size) {
    const float* x = (const float*)d_in[0];
    const float* w_src[7];
    const float* b_src[7];
    for (int i = 0; i < 7; i++) {
        w_src[i] = (const float*)d_in[1 + 2 * i];
        b_src[i] = (const float*)d_in[2 + 2 * i];
    }
    const float* ln1g = (const float*)d_in[15];
    const float* ln1b = (const float*)d_in[16];
    const float* ln2g = (const float*)d_in[17];
    const float* ln2b = (const float*)d_in[18];
    const float* mixk = (const float*)d_in[19];
    const float* mixv = (const float*)d_in[20];
    const float* mixr = (const float*)d_in[21];
    const float* fmk  = (const float*)d_in[22];
    const float* fmr  = (const float*)d_in[23];
    const float* tf   = (const float*)d_in[24];
    const float* td   = (const float*)d_in[25];
    float* out = (float*)d_out;

    __half *p_h0, *p_h1, *p_h2, *p_t0h, *p_rh, *p_kh, *p_vh, *p_rzh, *p_wh;
    cudaGetSymbolAddress((void**)&p_h0,  g_h0);
    cudaGetSymbolAddress((void**)&p_h1,  g_h1);
    cudaGetSymbolAddress((void**)&p_h2,  g_h2);
    cudaGetSymbolAddress((void**)&p_t0h, g_t0h);
    cudaGetSymbolAddress((void**)&p_rh,  g_rh);
    cudaGetSymbolAddress((void**)&p_kh,  g_kh);
    cudaGetSymbolAddress((void**)&p_vh,  g_vh);
    cudaGetSymbolAddress((void**)&p_rzh, g_rzh);
    cudaGetSymbolAddress((void**)&p_wh,  g_wh);

    cudaFuncSetAttribute(gemm_h, cudaFuncAttributeMaxDynamicSharedMemorySize, SMEM_DYN);

    cudaStream_t s2;
    cudaStreamCreateWithFlags(&s2, cudaStreamNonBlocking);
    cudaEvent_t ev0, evW, evM, evR;
    cudaEventCreateWithFlags(&ev0, cudaEventDisableTiming);
    cudaEventCreateWithFlags(&evW, cudaEventDisableTiming);
    cudaEventCreateWithFlags(&evM, cudaEventDisableTiming);
    cudaEventCreateWithFlags(&evR, cudaEventDisableTiming);

    dim3 gwkv(DD / 512, NCH);
    const __half* W[7];
    for (int i = 0; i < 7; i++) W[i] = p_wh + (size_t)i * DD * DD;

    cudaLaunchAttribute pdl_attr[1];
    pdl_attr[0].id = cudaLaunchAttributeProgrammaticStreamSerialization;
    pdl_attr[0].val.programmaticStreamSerializationAllowed = 1;
    auto launch_gemm_pdl = [&](dim3 grid, const GJobs& js, cudaStream_t st) {
        cudaLaunchConfig_t cfg{};
        cfg.gridDim = grid; cfg.blockDim = dim3(128, 1, 1);
        cfg.dynamicSmemBytes = SMEM_DYN; cfg.stream = st;
        cfg.attrs = pdl_attr; cfg.numAttrs = 1;
        cudaLaunchKernelEx(&cfg, gemm_h, js);
    };

    // fork: weight conversion on s2 (attn weights first -> early evW), ln_mix1 on main
    cudaEventRecord(ev0, 0);
    cudaStreamWaitEvent(s2, ev0, 0);
    {   // attn weights: W0 (attk), W1 (attv), W2 (attr)
        WConvJob wj{};
        wj.src[0] = (const float4*)w_src[0];
        wj.src[1] = (const float4*)w_src[1];
        wj.src[2] = (const float4*)w_src[2];
        wj.src[3] = (const float4*)w_src[2];   // unused (grid covers 3)
        wj.dst = (__half2*)p_wh;
        wconvN_kernel<<<3 * (DD * DD / 4) / 256, 256, 0, s2>>>(wj);
    }
    cudaEventRecord(evW, s2);
    {   // ffn-side weights: W3 (atto), W4 (ffnk), W5 (ffnv), W6 (ffnr)
        WConvJob wj{};
        wj.src[0] = (const float4*)w_src[3];
        wj.src[1] = (const float4*)w_src[4];
        wj.src[2] = (const float4*)w_src[5];
        wj.src[3] = (const float4*)w_src[6];
        wj.dst = (__half2*)(p_wh + (size_t)3 * DD * DD);
        wconvN_kernel<<<4 * (DD * DD / 4) / 256, 256, 0, s2>>>(wj);
    }

    ln_mix4_kernel<3, float><<<TT / 4, 256>>>(x, ln1g, ln1b, mixk, mixv, mixr,
                                              (__half2*)p_h0, (__half2*)p_h1, (__half2*)p_h2);
    cudaEventRecord(evM, 0);

    // s2: r GEMM (after both wconv launches in-stream, and ln_mix1 via evM)
    cudaStreamWaitEvent(s2, evM, 0);
    {
        GJobs js{};
        js.j[0] = { p_h2, W[2], b_src[2], nullptr, nullptr, nullptr, (void*)p_rh, 1 };
        gemm_h<<<dim3(TT / BM, DD / BN, 1), 128, SMEM_DYN, s2>>>(js);
    }
    cudaEventRecord(evR, s2);

    // main: kv GEMM (event-guarded on attn weights), then wkv1/2 (PDL)
    cudaStreamWaitEvent(0, evW, 0);
    {
        GJobs js{};
        js.j[0] = { p_h0, W[0], b_src[0], nullptr, nullptr, nullptr, (void*)p_kh, 0 };
        js.j[1] = { p_h1, W[1], b_src[1], nullptr, nullptr, nullptr, (void*)p_vh, 0 };
        gemm_h<<<dim3(TT / BM, DD / BN, 2), 128, SMEM_DYN>>>(js);
    }
    {
        cudaLaunchConfig_t cfg{};
        cfg.gridDim = gwkv; cfg.blockDim = dim3(256, 1, 1);
        cfg.dynamicSmemBytes = 0; cfg.stream = 0;
        cfg.attrs = pdl_attr; cfg.numAttrs = 1;
        cudaLaunchKernelEx(&cfg, wkv_phase1,
                           (const __half2*)p_kh, (const __half2*)p_vh, (const float2*)td);
    }
    {
        cudaLaunchConfig_t cfg{};
        cfg.gridDim = dim3(DD / 256, 1, 1); cfg.blockDim = dim3(256, 1, 1);
        cfg.dynamicSmemBytes = 0; cfg.stream = 0;
        cfg.attrs = pdl_attr; cfg.numAttrs = 1;
        cudaLaunchKernelEx(&cfg, wkv_phase2, td);
    }

    cudaStreamWaitEvent(0, evR, 0);   // join: wkv3 needs r
    wkv_phase3<<<gwkv, 256>>>((const __half2*)p_kh, (const __half2*)p_vh,
                              (const __half2*)p_rh, (const float2*)tf, (const float2*)td,
                              (__half2*)p_t0h);

    {   // atto GEMM + residual (rz -> half) — PDL after wkv3
        GJobs js{};
        js.j[0] = { p_t0h, W[3], b_src[3], x, nullptr, nullptr, (void*)p_rzh, 3 };
        launch_gemm_pdl(dim3(TT / BM, DD / BN, 1), js, 0);
    }

    // --- FFN branch — ln_mix2 PDL after atto ---
    {
        cudaLaunchConfig_t cfg{};
        cfg.gridDim = dim3(TT / 4, 1, 1); cfg.blockDim = dim3(256, 1, 1);
        cfg.dynamicSmemBytes = 0; cfg.stream = 0;
        cfg.attrs = pdl_attr; cfg.numAttrs = 1;
        cudaLaunchKernelEx(&cfg, ln_mix4_kernel<2, __half>,
                           (const __half*)p_rzh, ln2g, ln2b, fmr, fmk, (const float*)nullptr,
                           (__half2*)p_h0, (__half2*)p_h1, (__half2*)nullptr);
    }

    {   // fused ffnr (sigmoid->half) + ffnk (relu^2->half) — PDL after ln_mix2
        GJobs js{};
        js.j[0] = { p_h0, W[6], b_src[6], nullptr, nullptr, nullptr, (void*)p_rh,  1 };
        js.j[1] = { p_h1, W[4], b_src[4], nullptr, nullptr, nullptr, (void*)p_t0h, 2 };
        launch_gemm_pdl(dim3(TT / BM, DD / BN, 2), js, 0);
    }

    {   // ffnv GEMM + gating + residual (f32 out) — PDL after ffn pair
        GJobs js{};
        js.j[0] = { p_t0h, W[5], b_src[5], nullptr, p_rh, p_rzh, (void*)out, 4 };
        launch_gemm_pdl(dim3(TT / BM, DD / BN, 1), js, 0);
    }
}